// round 9
// baseline (speedup 1.0000x reference)
#include <cuda_runtime.h>
#include <cuda_fp16.h>
#include <math_constants.h>
#include <cstdint>

// Problem constants
#define NN   12288
#define DIM  128
#define HID  16
#define CLS  16

// Aggregation tiling
#define NSPLIT   12
#define COLS_PS  (NN / NSPLIT)     // 1024 columns per split
#define CHUNK    256               // columns staged per pass
#define ROWS_CTA 128               // 8 warps x 16 rows

// smem strides (fp16 elements), bank-conflict-free (verified lane maps)
#define S_N 24     // natural layout Hs[j][hid], j-stride
#define S_T 264    // transposed layout HsT[hid][j], hid-stride

#define SQRT_LOG2E 1.2011224087864498f   // sqrt(log2(e))

// Device scratch (no cudaMalloc allowed)
__device__ __align__(16) float g_Wc[DIM * CLS];               // combined weight
__device__ __align__(16) float g_bc[CLS];                     // combined bias
__device__ __align__(16) __half g_Hs[NN * HID];               // h * sqrt(log2e), fp16
__device__ __align__(16) float g_pnum[NSPLIT * NN * CLS];     // partial numerators (scaled)
__device__ __align__(16) float g_pden[NSPLIT * NN];           // partial denominators

// ---------------------------------------------------------------------------
// PTX helpers
// ---------------------------------------------------------------------------
__device__ __forceinline__ void mma_f16(float& d0, float& d1, float& d2, float& d3,
                                        uint32_t a0, uint32_t a1, uint32_t a2, uint32_t a3,
                                        uint32_t b0, uint32_t b1) {
    asm volatile(
        "mma.sync.aligned.m16n8k16.row.col.f32.f16.f16.f32 "
        "{%0,%1,%2,%3}, {%4,%5,%6,%7}, {%8,%9}, {%0,%1,%2,%3};"
        : "+f"(d0), "+f"(d1), "+f"(d2), "+f"(d3)
        : "r"(a0), "r"(a1), "r"(a2), "r"(a3), "r"(b0), "r"(b1));
}

// packs {lo, hi} -> f16x2 register (lo in low 16 bits)
__device__ __forceinline__ uint32_t cvt_f16x2(float lo, float hi) {
    uint32_t r;
    asm("cvt.rn.f16x2.f32 %0, %1, %2;" : "=r"(r) : "f"(hi), "f"(lo));
    return r;
}

__device__ __forceinline__ __half2 u2h(uint32_t v) { return *reinterpret_cast<__half2*>(&v); }
__device__ __forceinline__ uint32_t h2u(__half2 v) { return *reinterpret_cast<uint32_t*>(&v); }

// masked exp on a packed fp16 pair: e = (s > 0) ? 2^s : 0
__device__ __forceinline__ uint32_t masked_exp2h(uint32_t ps) {
    uint32_t pe;
    asm("ex2.approx.f16x2 %0, %1;" : "=r"(pe) : "r"(ps));
    const __half2 z2 = __half2(__ushort_as_half(0), __ushort_as_half(0));
    __half2 m = __hgt2(u2h(ps), z2);   // 1.0 / 0.0 per half
    return h2u(__hmul2(u2h(pe), m));
}

// ---------------------------------------------------------------------------
// Kernel 0: combined linear weights (layers are purely linear: no activation).
// Wc = W1 @ W2 @ W3 ; bc = (b1 @ W2 + b2) @ W3 + b3.  One block, 128 threads.
// ---------------------------------------------------------------------------
__global__ void precompute_kernel(const float* __restrict__ W1, const float* __restrict__ b1,
                                  const float* __restrict__ W2, const float* __restrict__ b2,
                                  const float* __restrict__ W3, const float* __restrict__ b3) {
    __shared__ float sW2[HID * HID];
    __shared__ float sW3[HID * CLS];
    const int t = threadIdx.x;
    for (int i = t; i < HID * HID; i += 128) sW2[i] = W2[i];
    for (int i = t; i < HID * CLS; i += 128) sW3[i] = W3[i];
    __syncthreads();

    // thread k computes row k of Wc
    float v[HID];
#pragma unroll
    for (int j = 0; j < HID; j++) v[j] = 0.f;
#pragma unroll
    for (int p = 0; p < HID; p++) {
        const float w = W1[t * HID + p];
#pragma unroll
        for (int j = 0; j < HID; j++) v[j] = fmaf(w, sW2[p * HID + j], v[j]);
    }
    float w[CLS];
#pragma unroll
    for (int j = 0; j < CLS; j++) w[j] = 0.f;
#pragma unroll
    for (int p = 0; p < HID; p++) {
#pragma unroll
        for (int j = 0; j < CLS; j++) w[j] = fmaf(v[p], sW3[p * CLS + j], w[j]);
    }
#pragma unroll
    for (int j = 0; j < CLS; j++) g_Wc[t * CLS + j] = w[j];

    if (t == 0) {
        float u[HID];
#pragma unroll
        for (int j = 0; j < HID; j++) u[j] = b2[j];
#pragma unroll
        for (int p = 0; p < HID; p++)
#pragma unroll
            for (int j = 0; j < HID; j++) u[j] = fmaf(b1[p], sW2[p * HID + j], u[j]);
        float bb[CLS];
#pragma unroll
        for (int j = 0; j < CLS; j++) bb[j] = b3[j];
#pragma unroll
        for (int p = 0; p < HID; p++)
#pragma unroll
            for (int j = 0; j < CLS; j++) bb[j] = fmaf(u[p], sW3[p * CLS + j], bb[j]);
#pragma unroll
        for (int j = 0; j < CLS; j++) g_bc[j] = bb[j];
    }
}

// ---------------------------------------------------------------------------
// Kernel 1: h = x @ Wc + bc -> g_Hs = fp16(h * sqrt(log2e)).
// One thread per (row, class): 768 CTAs x 256 threads for high occupancy.
// ---------------------------------------------------------------------------
__global__ __launch_bounds__(256)
void mlp_gemm(const float* __restrict__ x) {
    __shared__ float sWc[DIM * CLS];   // 8 KB
    __shared__ float sbc[CLS];

    const int tid = threadIdx.x;
    {
        const float4* src = reinterpret_cast<const float4*>(g_Wc);
        float4* dst = reinterpret_cast<float4*>(sWc);
        dst[tid]       = src[tid];
        dst[tid + 256] = src[tid + 256];
        if (tid < CLS) sbc[tid] = g_bc[tid];
    }
    __syncthreads();

    const int row = blockIdx.x * 16 + (tid >> 4);
    const int j   = tid & 15;

    const float4* xr = reinterpret_cast<const float4*>(x + (size_t)row * DIM);
    float a0 = 0.f, a1 = 0.f, a2 = 0.f, a3 = 0.f;
#pragma unroll
    for (int k4 = 0; k4 < 32; k4++) {
        const float4 xv = __ldg(&xr[k4]);
        a0 = fmaf(xv.x, sWc[(4 * k4 + 0) * CLS + j], a0);
        a1 = fmaf(xv.y, sWc[(4 * k4 + 1) * CLS + j], a1);
        a2 = fmaf(xv.z, sWc[(4 * k4 + 2) * CLS + j], a2);
        a3 = fmaf(xv.w, sWc[(4 * k4 + 3) * CLS + j], a3);
    }
    const float h = (a0 + a1) + (a2 + a3) + sbc[j];

    g_Hs[(size_t)row * HID + j] = __float2half(h * SQRT_LOG2E);
}

// ---------------------------------------------------------------------------
// Kernel 2: fused masked-softmax aggregation on tensor cores (fp16).
// S' = Hs @ Hs^T = log2e * (h_i . h_j) via f16 HMMA (fp32 accum);
// e  = (s'>0) ? 2^s' : 0 via packed f16x2 ex2 + packed mask;
// O' += P @ Hs (scaled by sqrt(log2e), corrected in finalize);
// den via packed HADD2 on the fma pipe (keeps the tensor pipe at 4 MMA/kc).
// ---------------------------------------------------------------------------
__global__ __launch_bounds__(256, 3)
void agg_kernel() {
    __shared__ __align__(16) __half sHn[CHUNK * S_N];  // Hs[j][hid]
    __shared__ __align__(16) __half sHt[HID * S_T];    // Hs^T[hid][j]

    const int tid  = threadIdx.x;
    const int lane = tid & 31;
    const int wid  = tid >> 5;        // 0..7
    const int g    = lane >> 2;       // 0..7
    const int t4   = lane & 3;        // 0..3

    const int split = blockIdx.y;
    const int rbase = blockIdx.x * ROWS_CTA + wid * 16;
    const int rg  = rbase + g;
    const int rg8 = rg + 8;

    // A-fragment: scaled rows (loop-invariant)
    uint32_t a0 = *reinterpret_cast<const uint32_t*>(g_Hs + (size_t)rg  * HID + 2 * t4);
    uint32_t a1 = *reinterpret_cast<const uint32_t*>(g_Hs + (size_t)rg8 * HID + 2 * t4);
    uint32_t a2 = *reinterpret_cast<const uint32_t*>(g_Hs + (size_t)rg  * HID + 2 * t4 + 8);
    uint32_t a3 = *reinterpret_cast<const uint32_t*>(g_Hs + (size_t)rg8 * HID + 2 * t4 + 8);

    float o00 = 0.f, o01 = 0.f, o02 = 0.f, o03 = 0.f;
    float o10 = 0.f, o11 = 0.f, o12 = 0.f, o13 = 0.f;
    // packed fp16 den accumulators (row g / row g+8); max ~12k < 65504, and
    // den precision is damped by log-softmax scale-invariance (see theory).
    __half2 dga = __half2(__ushort_as_half(0), __ushort_as_half(0));
    __half2 dgb = dga;

    const int j0 = split * COLS_PS;

    for (int cc = 0; cc < COLS_PS; cc += CHUNK) {
        __syncthreads();
        // Stage: thread `tid` owns column j = tid of this chunk.
        {
            const int j = tid;
            const size_t gidx = (size_t)(j0 + cc + j) * HID;
            const uint4 vs0 = *reinterpret_cast<const uint4*>(g_Hs + gidx);
            const uint4 vs1 = *reinterpret_cast<const uint4*>(g_Hs + gidx + 8);
            *reinterpret_cast<uint4*>(&sHn[j * S_N])     = vs0;
            *reinterpret_cast<uint4*>(&sHn[j * S_N + 8]) = vs1;

            const uint32_t u[8] = {vs0.x, vs0.y, vs0.z, vs0.w, vs1.x, vs1.y, vs1.z, vs1.w};
#pragma unroll
            for (int w = 0; w < 8; w++) {
                __half2 bp = u2h(u[w]);
                sHt[(2 * w)     * S_T + j] = bp.x;
                sHt[(2 * w + 1) * S_T + j] = bp.y;
            }
        }
        __syncthreads();

#pragma unroll
        for (int kc = 0; kc < CHUNK / 16; kc++) {
            const int ja = 16 * kc + g;
            const int jb = ja + 8;
            uint32_t b0a = *reinterpret_cast<const uint32_t*>(&sHn[ja * S_N + 2 * t4]);
            uint32_t b1a = *reinterpret_cast<const uint32_t*>(&sHn[ja * S_N + 2 * t4 + 8]);
            uint32_t b0b = *reinterpret_cast<const uint32_t*>(&sHn[jb * S_N + 2 * t4]);
            uint32_t b1b = *reinterpret_cast<const uint32_t*>(&sHn[jb * S_N + 2 * t4 + 8]);

            float s0 = 0.f, s1 = 0.f, s2 = 0.f, s3 = 0.f;
            float s4 = 0.f, s5 = 0.f, s6 = 0.f, s7 = 0.f;
            mma_f16(s0, s1, s2, s3, a0, a1, a2, a3, b0a, b1a);
            mma_f16(s4, s5, s6, s7, a0, a1, a2, a3, b0b, b1b);

            // pack s -> f16x2, then packed masked exp
            uint32_t pa0 = masked_exp2h(cvt_f16x2(s0, s1));   // P[g   ][2t4..]
            uint32_t pa1 = masked_exp2h(cvt_f16x2(s2, s3));   // P[g+8 ][2t4..]
            uint32_t pa2 = masked_exp2h(cvt_f16x2(s4, s5));   // P[g   ][8+2t4..]
            uint32_t pa3 = masked_exp2h(cvt_f16x2(s6, s7));   // P[g+8 ][8+2t4..]

            // den on the fma pipe: 4 HADD2/kc
            dga = __hadd2(dga, __hadd2(u2h(pa0), u2h(pa2)));
            dgb = __hadd2(dgb, __hadd2(u2h(pa1), u2h(pa3)));

            uint32_t q0n0 = *reinterpret_cast<const uint32_t*>(&sHt[g * S_T + 16 * kc + 2 * t4]);
            uint32_t q1n0 = *reinterpret_cast<const uint32_t*>(&sHt[g * S_T + 16 * kc + 2 * t4 + 8]);
            uint32_t q0n1 = *reinterpret_cast<const uint32_t*>(&sHt[(g + 8) * S_T + 16 * kc + 2 * t4]);
            uint32_t q1n1 = *reinterpret_cast<const uint32_t*>(&sHt[(g + 8) * S_T + 16 * kc + 2 * t4 + 8]);

            mma_f16(o00, o01, o02, o03, pa0, pa1, pa2, pa3, q0n0, q1n0);
            mma_f16(o10, o11, o12, o13, pa0, pa1, pa2, pa3, q0n1, q1n1);
        }
    }

    // den epilogue: unpack to f32, reduce across the 4 lanes sharing each row
    float den_g  = __half2float(dga.x) + __half2float(dga.y);
    float den_g8 = __half2float(dgb.x) + __half2float(dgb.y);
    den_g  += __shfl_xor_sync(0xffffffffu, den_g, 1);
    den_g  += __shfl_xor_sync(0xffffffffu, den_g, 2);
    den_g8 += __shfl_xor_sync(0xffffffffu, den_g8, 1);
    den_g8 += __shfl_xor_sync(0xffffffffu, den_g8, 2);

    float* pn  = g_pnum + ((size_t)split * NN + rg) * CLS;
    float* pn8 = g_pnum + ((size_t)split * NN + rg8) * CLS;
    *reinterpret_cast<float2*>(&pn [2 * t4])     = make_float2(o00, o01);
    *reinterpret_cast<float2*>(&pn [2 * t4 + 8]) = make_float2(o10, o11);
    *reinterpret_cast<float2*>(&pn8[2 * t4])     = make_float2(o02, o03);
    *reinterpret_cast<float2*>(&pn8[2 * t4 + 8]) = make_float2(o12, o13);
    if (t4 == 0) {
        g_pden[split * NN + rg]  = den_g;
        g_pden[split * NN + rg8] = den_g8;
    }
}

// ---------------------------------------------------------------------------
// Kernel 3: reduce split partials, out = num/(den*sqrt(log2e)), row log-softmax.
// 8 threads per row; each owns 2 classes; 8-lane shuffle-reduce for max/lse.
// ---------------------------------------------------------------------------
__global__ __launch_bounds__(256)
void finalize_kernel(float* __restrict__ out) {
    const int idx = blockIdx.x * 256 + threadIdx.x;
    const int row = idx >> 3;
    const int p   = idx & 7;

    float n0 = 0.f, n1 = 0.f, den = 0.f;
#pragma unroll
    for (int s = 0; s < NSPLIT; s++) {
        float2 v = *reinterpret_cast<const float2*>(
            g_pnum + ((size_t)s * NN + row) * CLS + 2 * p);
        n0 += v.x; n1 += v.y;
        den += g_pden[s * NN + row];
    }

    // num is scaled by sqrt(log2e) (O-mma used scaled Hs); correct here.
    const float inv = 1.0f / (den * SQRT_LOG2E);
    float o0 = n0 * inv, o1 = n1 * inv;

    float m = fmaxf(o0, o1);
    m = fmaxf(m, __shfl_xor_sync(0xffffffffu, m, 1));
    m = fmaxf(m, __shfl_xor_sync(0xffffffffu, m, 2));
    m = fmaxf(m, __shfl_xor_sync(0xffffffffu, m, 4));

    float sum = expf(o0 - m) + expf(o1 - m);
    sum += __shfl_xor_sync(0xffffffffu, sum, 1);
    sum += __shfl_xor_sync(0xffffffffu, sum, 2);
    sum += __shfl_xor_sync(0xffffffffu, sum, 4);

    const float lse = logf(sum) + m;
    *reinterpret_cast<float2*>(out + (size_t)row * CLS + 2 * p) =
        make_float2(o0 - lse, o1 - lse);
}

// ---------------------------------------------------------------------------
extern "C" void kernel_launch(void* const* d_in, const int* in_sizes, int n_in,
                              void* d_out, int out_size) {
    const float* x  = (const float*)d_in[0];
    const float* W1 = (const float*)d_in[1];
    const float* b1 = (const float*)d_in[2];
    const float* W2 = (const float*)d_in[3];
    const float* b2 = (const float*)d_in[4];
    const float* W3 = (const float*)d_in[5];
    const float* b3 = (const float*)d_in[6];
    float* out = (float*)d_out;

    precompute_kernel<<<1, 128>>>(W1, b1, W2, b2, W3, b3);
    mlp_gemm<<<NN / 16, 256>>>(x);

    dim3 grid(NN / ROWS_CTA, NSPLIT);
    agg_kernel<<<grid, 256>>>();

    finalize_kernel<<<(NN * 8) / 256, 256>>>(out);
}

// round 10
// speedup vs baseline: 1.0366x; 1.0366x over previous
#include <cuda_runtime.h>
#include <cuda_fp16.h>
#include <math_constants.h>
#include <cstdint>

// Problem constants
#define NN   12288
#define DIM  128
#define HID  16
#define CLS  16

// Aggregation tiling
#define NSPLIT   12
#define COLS_PS  (NN / NSPLIT)     // 1024 columns per split
#define CHUNK    256               // columns staged per pass
#define ROWS_CTA 128               // 8 warps x 16 rows

// smem strides (fp16 elements), bank-conflict-free (verified lane maps)
#define S_N 24     // natural layout Hs[j][hid], j-stride
#define S_T 264    // transposed layout HsT[hid][j], hid-stride

#define SQRT_LOG2E 1.2011224087864498f   // sqrt(log2(e))

// Device scratch (no cudaMalloc allowed)
__device__ __align__(16) float g_Wc[DIM * CLS];               // combined weight
__device__ __align__(16) float g_bc[CLS];                     // combined bias
__device__ __align__(16) __half g_Hs[NN * HID];               // h * sqrt(log2e), fp16
__device__ __align__(16) float g_pnum[NSPLIT * NN * CLS];     // partial numerators (scaled)
__device__ __align__(16) float g_pden[NSPLIT * NN];           // partial denominators

// ---------------------------------------------------------------------------
// PTX helpers
// ---------------------------------------------------------------------------
__device__ __forceinline__ void mma_f16(float& d0, float& d1, float& d2, float& d3,
                                        uint32_t a0, uint32_t a1, uint32_t a2, uint32_t a3,
                                        uint32_t b0, uint32_t b1) {
    asm volatile(
        "mma.sync.aligned.m16n8k16.row.col.f32.f16.f16.f32 "
        "{%0,%1,%2,%3}, {%4,%5,%6,%7}, {%8,%9}, {%0,%1,%2,%3};"
        : "+f"(d0), "+f"(d1), "+f"(d2), "+f"(d3)
        : "r"(a0), "r"(a1), "r"(a2), "r"(a3), "r"(b0), "r"(b1));
}

// fp16-accumulator variant: D/C fragments are two packed f16x2 registers.
// c0 = row g,   cols {2t4, 2t4+1};  c1 = row g+8, same cols  (n8 tile)
__device__ __forceinline__ void mma_f16acc(uint32_t& c0, uint32_t& c1,
                                           uint32_t a0, uint32_t a1, uint32_t a2, uint32_t a3,
                                           uint32_t b0, uint32_t b1) {
    asm volatile(
        "mma.sync.aligned.m16n8k16.row.col.f16.f16.f16.f16 "
        "{%0,%1}, {%2,%3,%4,%5}, {%6,%7}, {%0,%1};"
        : "+r"(c0), "+r"(c1)
        : "r"(a0), "r"(a1), "r"(a2), "r"(a3), "r"(b0), "r"(b1));
}

__device__ __forceinline__ __half2 u2h(uint32_t v) { return *reinterpret_cast<__half2*>(&v); }
__device__ __forceinline__ uint32_t h2u(__half2 v) { return *reinterpret_cast<uint32_t*>(&v); }

// masked exp on a packed fp16 pair: e = (s > 0) ? 2^s : 0
__device__ __forceinline__ uint32_t masked_exp2h(uint32_t ps) {
    uint32_t pe;
    asm("ex2.approx.f16x2 %0, %1;" : "=r"(pe) : "r"(ps));
    const __half2 z2 = __half2(__ushort_as_half(0), __ushort_as_half(0));
    __half2 m = __hgt2(u2h(ps), z2);   // 1.0 / 0.0 per half
    return h2u(__hmul2(u2h(pe), m));
}

// ---------------------------------------------------------------------------
// Kernel 0: combined linear weights (layers are purely linear: no activation).
// Wc = W1 @ W2 @ W3 ; bc = (b1 @ W2 + b2) @ W3 + b3.  One block, 128 threads.
// ---------------------------------------------------------------------------
__global__ void precompute_kernel(const float* __restrict__ W1, const float* __restrict__ b1,
                                  const float* __restrict__ W2, const float* __restrict__ b2,
                                  const float* __restrict__ W3, const float* __restrict__ b3) {
    __shared__ float sW2[HID * HID];
    __shared__ float sW3[HID * CLS];
    const int t = threadIdx.x;
    for (int i = t; i < HID * HID; i += 128) sW2[i] = W2[i];
    for (int i = t; i < HID * CLS; i += 128) sW3[i] = W3[i];
    __syncthreads();

    // thread k computes row k of Wc
    float v[HID];
#pragma unroll
    for (int j = 0; j < HID; j++) v[j] = 0.f;
#pragma unroll
    for (int p = 0; p < HID; p++) {
        const float w = W1[t * HID + p];
#pragma unroll
        for (int j = 0; j < HID; j++) v[j] = fmaf(w, sW2[p * HID + j], v[j]);
    }
    float w[CLS];
#pragma unroll
    for (int j = 0; j < CLS; j++) w[j] = 0.f;
#pragma unroll
    for (int p = 0; p < HID; p++) {
#pragma unroll
        for (int j = 0; j < CLS; j++) w[j] = fmaf(v[p], sW3[p * CLS + j], w[j]);
    }
#pragma unroll
    for (int j = 0; j < CLS; j++) g_Wc[t * CLS + j] = w[j];

    if (t == 0) {
        float u[HID];
#pragma unroll
        for (int j = 0; j < HID; j++) u[j] = b2[j];
#pragma unroll
        for (int p = 0; p < HID; p++)
#pragma unroll
            for (int j = 0; j < HID; j++) u[j] = fmaf(b1[p], sW2[p * HID + j], u[j]);
        float bb[CLS];
#pragma unroll
        for (int j = 0; j < CLS; j++) bb[j] = b3[j];
#pragma unroll
        for (int p = 0; p < HID; p++)
#pragma unroll
            for (int j = 0; j < CLS; j++) bb[j] = fmaf(u[p], sW3[p * CLS + j], bb[j]);
#pragma unroll
        for (int j = 0; j < CLS; j++) g_bc[j] = bb[j];
    }
}

// ---------------------------------------------------------------------------
// Kernel 1: h = x @ Wc + bc -> g_Hs = fp16(h * sqrt(log2e)).
// One thread per (row, class): 768 CTAs x 256 threads for high occupancy.
// ---------------------------------------------------------------------------
__global__ __launch_bounds__(256)
void mlp_gemm(const float* __restrict__ x) {
    __shared__ float sWc[DIM * CLS];   // 8 KB
    __shared__ float sbc[CLS];

    const int tid = threadIdx.x;
    {
        const float4* src = reinterpret_cast<const float4*>(g_Wc);
        float4* dst = reinterpret_cast<float4*>(sWc);
        dst[tid]       = src[tid];
        dst[tid + 256] = src[tid + 256];
        if (tid < CLS) sbc[tid] = g_bc[tid];
    }
    __syncthreads();

    const int row = blockIdx.x * 16 + (tid >> 4);
    const int j   = tid & 15;

    const float4* xr = reinterpret_cast<const float4*>(x + (size_t)row * DIM);
    float a0 = 0.f, a1 = 0.f, a2 = 0.f, a3 = 0.f;
#pragma unroll
    for (int k4 = 0; k4 < 32; k4++) {
        const float4 xv = __ldg(&xr[k4]);
        a0 = fmaf(xv.x, sWc[(4 * k4 + 0) * CLS + j], a0);
        a1 = fmaf(xv.y, sWc[(4 * k4 + 1) * CLS + j], a1);
        a2 = fmaf(xv.z, sWc[(4 * k4 + 2) * CLS + j], a2);
        a3 = fmaf(xv.w, sWc[(4 * k4 + 3) * CLS + j], a3);
    }
    const float h = (a0 + a1) + (a2 + a3) + sbc[j];

    g_Hs[(size_t)row * HID + j] = __float2half(h * SQRT_LOG2E);
}

// ---------------------------------------------------------------------------
// Kernel 2: fused masked-softmax aggregation on tensor cores (fp16).
// S' = Hs @ Hs^T via f16 HMMA with FP16 accumulators -> packed pairs directly;
// e  = (s'>0) ? 2^s' : 0 via packed f16x2 ex2 + packed mask;
// O' += P @ Hs (f32 accum; scaled by sqrt(log2e), corrected in finalize);
// den via packed HADD2 on the fma pipe.
// 4 CTAs/SM for latency coverage (8 warps/SMSP).
// ---------------------------------------------------------------------------
__global__ __launch_bounds__(256, 4)
void agg_kernel() {
    __shared__ __align__(16) __half sHn[CHUNK * S_N];  // Hs[j][hid]
    __shared__ __align__(16) __half sHt[HID * S_T];    // Hs^T[hid][j]

    const int tid  = threadIdx.x;
    const int lane = tid & 31;
    const int wid  = tid >> 5;        // 0..7
    const int g    = lane >> 2;       // 0..7
    const int t4   = lane & 3;        // 0..3

    const int split = blockIdx.y;
    const int rbase = blockIdx.x * ROWS_CTA + wid * 16;
    const int rg  = rbase + g;
    const int rg8 = rg + 8;

    // A-fragment: scaled rows (loop-invariant)
    uint32_t a0 = *reinterpret_cast<const uint32_t*>(g_Hs + (size_t)rg  * HID + 2 * t4);
    uint32_t a1 = *reinterpret_cast<const uint32_t*>(g_Hs + (size_t)rg8 * HID + 2 * t4);
    uint32_t a2 = *reinterpret_cast<const uint32_t*>(g_Hs + (size_t)rg  * HID + 2 * t4 + 8);
    uint32_t a3 = *reinterpret_cast<const uint32_t*>(g_Hs + (size_t)rg8 * HID + 2 * t4 + 8);

    float o00 = 0.f, o01 = 0.f, o02 = 0.f, o03 = 0.f;
    float o10 = 0.f, o11 = 0.f, o12 = 0.f, o13 = 0.f;
    // packed fp16 den accumulators (rows g / g+8 interleaved in pairs)
    __half2 dga = __half2(__ushort_as_half(0), __ushort_as_half(0));
    __half2 dgb = dga;

    const int j0 = split * COLS_PS;

    for (int cc = 0; cc < COLS_PS; cc += CHUNK) {
        __syncthreads();
        // Stage: thread `tid` owns column j = tid of this chunk.
        {
            const int j = tid;
            const size_t gidx = (size_t)(j0 + cc + j) * HID;
            const uint4 vs0 = *reinterpret_cast<const uint4*>(g_Hs + gidx);
            const uint4 vs1 = *reinterpret_cast<const uint4*>(g_Hs + gidx + 8);
            *reinterpret_cast<uint4*>(&sHn[j * S_N])     = vs0;
            *reinterpret_cast<uint4*>(&sHn[j * S_N + 8]) = vs1;

            const uint32_t u[8] = {vs0.x, vs0.y, vs0.z, vs0.w, vs1.x, vs1.y, vs1.z, vs1.w};
#pragma unroll
            for (int w = 0; w < 8; w++) {
                __half2 bp = u2h(u[w]);
                sHt[(2 * w)     * S_T + j] = bp.x;
                sHt[(2 * w + 1) * S_T + j] = bp.y;
            }
        }
        __syncthreads();

#pragma unroll
        for (int kc = 0; kc < CHUNK / 16; kc++) {
            const int ja = 16 * kc + g;
            const int jb = ja + 8;
            uint32_t b0a = *reinterpret_cast<const uint32_t*>(&sHn[ja * S_N + 2 * t4]);
            uint32_t b1a = *reinterpret_cast<const uint32_t*>(&sHn[ja * S_N + 2 * t4 + 8]);
            uint32_t b0b = *reinterpret_cast<const uint32_t*>(&sHn[jb * S_N + 2 * t4]);
            uint32_t b1b = *reinterpret_cast<const uint32_t*>(&sHn[jb * S_N + 2 * t4 + 8]);

            // S-mma with fp16 accumulators: D-fragment IS the packed pair layout
            uint32_t c0a = 0u, c1a = 0u, c0b = 0u, c1b = 0u;
            mma_f16acc(c0a, c1a, a0, a1, a2, a3, b0a, b1a);
            mma_f16acc(c0b, c1b, a0, a1, a2, a3, b0b, b1b);

            // packed masked exp straight off the MMA output
            uint32_t pa0 = masked_exp2h(c0a);   // P[g   ][2t4..]   (n-tile a)
            uint32_t pa1 = masked_exp2h(c1a);   // P[g+8 ][2t4..]
            uint32_t pa2 = masked_exp2h(c0b);   // P[g   ][8+2t4..] (n-tile b)
            uint32_t pa3 = masked_exp2h(c1b);   // P[g+8 ][8+2t4..]

            // den on the fma pipe: 4 HADD2/kc
            dga = __hadd2(dga, __hadd2(u2h(pa0), u2h(pa2)));
            dgb = __hadd2(dgb, __hadd2(u2h(pa1), u2h(pa3)));

            uint32_t q0n0 = *reinterpret_cast<const uint32_t*>(&sHt[g * S_T + 16 * kc + 2 * t4]);
            uint32_t q1n0 = *reinterpret_cast<const uint32_t*>(&sHt[g * S_T + 16 * kc + 2 * t4 + 8]);
            uint32_t q0n1 = *reinterpret_cast<const uint32_t*>(&sHt[(g + 8) * S_T + 16 * kc + 2 * t4]);
            uint32_t q1n1 = *reinterpret_cast<const uint32_t*>(&sHt[(g + 8) * S_T + 16 * kc + 2 * t4 + 8]);

            mma_f16(o00, o01, o02, o03, pa0, pa1, pa2, pa3, q0n0, q1n0);
            mma_f16(o10, o11, o12, o13, pa0, pa1, pa2, pa3, q0n1, q1n1);
        }
    }

    // den epilogue: unpack to f32, reduce across the 4 lanes sharing each row
    float den_g  = __half2float(dga.x) + __half2float(dga.y);
    float den_g8 = __half2float(dgb.x) + __half2float(dgb.y);
    den_g  += __shfl_xor_sync(0xffffffffu, den_g, 1);
    den_g  += __shfl_xor_sync(0xffffffffu, den_g, 2);
    den_g8 += __shfl_xor_sync(0xffffffffu, den_g8, 1);
    den_g8 += __shfl_xor_sync(0xffffffffu, den_g8, 2);

    float* pn  = g_pnum + ((size_t)split * NN + rg) * CLS;
    float* pn8 = g_pnum + ((size_t)split * NN + rg8) * CLS;
    *reinterpret_cast<float2*>(&pn [2 * t4])     = make_float2(o00, o01);
    *reinterpret_cast<float2*>(&pn [2 * t4 + 8]) = make_float2(o10, o11);
    *reinterpret_cast<float2*>(&pn8[2 * t4])     = make_float2(o02, o03);
    *reinterpret_cast<float2*>(&pn8[2 * t4 + 8]) = make_float2(o12, o13);
    if (t4 == 0) {
        g_pden[split * NN + rg]  = den_g;
        g_pden[split * NN + rg8] = den_g8;
    }
}

// ---------------------------------------------------------------------------
// Kernel 3: reduce split partials, out = num/(den*sqrt(log2e)), row log-softmax.
// 8 threads per row; each owns 2 classes; 8-lane shuffle-reduce for max/lse.
// ---------------------------------------------------------------------------
__global__ __launch_bounds__(256)
void finalize_kernel(float* __restrict__ out) {
    const int idx = blockIdx.x * 256 + threadIdx.x;
    const int row = idx >> 3;
    const int p   = idx & 7;

    float n0 = 0.f, n1 = 0.f, den = 0.f;
#pragma unroll
    for (int s = 0; s < NSPLIT; s++) {
        float2 v = *reinterpret_cast<const float2*>(
            g_pnum + ((size_t)s * NN + row) * CLS + 2 * p);
        n0 += v.x; n1 += v.y;
        den += g_pden[s * NN + row];
    }

    // num is scaled by sqrt(log2e) (O-mma used scaled Hs); correct here.
    const float inv = 1.0f / (den * SQRT_LOG2E);
    float o0 = n0 * inv, o1 = n1 * inv;

    float m = fmaxf(o0, o1);
    m = fmaxf(m, __shfl_xor_sync(0xffffffffu, m, 1));
    m = fmaxf(m, __shfl_xor_sync(0xffffffffu, m, 2));
    m = fmaxf(m, __shfl_xor_sync(0xffffffffu, m, 4));

    float sum = expf(o0 - m) + expf(o1 - m);
    sum += __shfl_xor_sync(0xffffffffu, sum, 1);
    sum += __shfl_xor_sync(0xffffffffu, sum, 2);
    sum += __shfl_xor_sync(0xffffffffu, sum, 4);

    const float lse = logf(sum) + m;
    *reinterpret_cast<float2*>(out + (size_t)row * CLS + 2 * p) =
        make_float2(o0 - lse, o1 - lse);
}

// ---------------------------------------------------------------------------
extern "C" void kernel_launch(void* const* d_in, const int* in_sizes, int n_in,
                              void* d_out, int out_size) {
    const float* x  = (const float*)d_in[0];
    const float* W1 = (const float*)d_in[1];
    const float* b1 = (const float*)d_in[2];
    const float* W2 = (const float*)d_in[3];
    const float* b2 = (const float*)d_in[4];
    const float* W3 = (const float*)d_in[5];
    const float* b3 = (const float*)d_in[6];
    float* out = (float*)d_out;

    precompute_kernel<<<1, 128>>>(W1, b1, W2, b2, W3, b3);
    mlp_gemm<<<NN / 16, 256>>>(x);

    dim3 grid(NN / ROWS_CTA, NSPLIT);
    agg_kernel<<<grid, 256>>>();

    finalize_kernel<<<(NN * 8) / 256, 256>>>(out);
}

// round 11
// speedup vs baseline: 1.0407x; 1.0040x over previous
#include <cuda_runtime.h>
#include <cuda_fp16.h>
#include <math_constants.h>
#include <cstdint>

// Problem constants
#define NN   12288
#define DIM  128
#define HID  16
#define CLS  16

// Aggregation tiling
#define NSPLIT   6
#define COLS_PS  (NN / NSPLIT)     // 2048 columns per split
#define CHUNK    256               // columns staged per pass
#define ROWS_CTA 128               // 8 warps x 16 rows
// grid = (NN/ROWS_CTA) * NSPLIT = 96*6 = 576 CTAs = one full wave at occ 4

// smem strides (fp16 elements), bank-conflict-free (verified lane maps)
#define S_N 24     // natural layout Hs[j][hid], j-stride
#define S_T 264    // transposed layout HsT[hid][j], hid-stride

#define SQRT_LOG2E 1.2011224087864498f   // sqrt(log2(e))

// Device scratch (no cudaMalloc allowed)
__device__ __align__(16) float g_Wc[DIM * CLS];               // combined weight
__device__ __align__(16) float g_bc[CLS];                     // combined bias
__device__ __align__(16) __half g_Hs[NN * HID];               // h * sqrt(log2e), fp16
__device__ __align__(16) float g_pnum[NSPLIT * NN * CLS];     // partial numerators (scaled)
__device__ __align__(16) float g_pden[NSPLIT * NN];           // partial denominators

// ---------------------------------------------------------------------------
// PTX helpers
// ---------------------------------------------------------------------------
__device__ __forceinline__ void mma_f16(float& d0, float& d1, float& d2, float& d3,
                                        uint32_t a0, uint32_t a1, uint32_t a2, uint32_t a3,
                                        uint32_t b0, uint32_t b1) {
    asm volatile(
        "mma.sync.aligned.m16n8k16.row.col.f32.f16.f16.f32 "
        "{%0,%1,%2,%3}, {%4,%5,%6,%7}, {%8,%9}, {%0,%1,%2,%3};"
        : "+f"(d0), "+f"(d1), "+f"(d2), "+f"(d3)
        : "r"(a0), "r"(a1), "r"(a2), "r"(a3), "r"(b0), "r"(b1));
}

// fp16-accumulator variant: D/C fragments are two packed f16x2 registers.
// c0 = rows 0-7 (g), cols {2t4, 2t4+1}; c1 = rows 8-15 (g+8), same cols
__device__ __forceinline__ void mma_f16acc(uint32_t& c0, uint32_t& c1,
                                           uint32_t a0, uint32_t a1, uint32_t a2, uint32_t a3,
                                           uint32_t b0, uint32_t b1) {
    asm volatile(
        "mma.sync.aligned.m16n8k16.row.col.f16.f16.f16.f16 "
        "{%0,%1}, {%2,%3,%4,%5}, {%6,%7}, {%0,%1};"
        : "+r"(c0), "+r"(c1)
        : "r"(a0), "r"(a1), "r"(a2), "r"(a3), "r"(b0), "r"(b1));
}

__device__ __forceinline__ __half2 u2h(uint32_t v) { return *reinterpret_cast<__half2*>(&v); }
__device__ __forceinline__ uint32_t h2u(__half2 v) { return *reinterpret_cast<uint32_t*>(&v); }

// masked exp on a packed fp16 pair: e = (s > 0) ? 2^s : 0
__device__ __forceinline__ uint32_t masked_exp2h(uint32_t ps) {
    uint32_t pe;
    asm("ex2.approx.f16x2 %0, %1;" : "=r"(pe) : "r"(ps));
    const __half2 z2 = __half2(__ushort_as_half(0), __ushort_as_half(0));
    __half2 m = __hgt2(u2h(ps), z2);   // 1.0 / 0.0 per half
    return h2u(__hmul2(u2h(pe), m));
}

// ---------------------------------------------------------------------------
// Kernel 0: combined linear weights (layers are purely linear: no activation).
// Wc = W1 @ W2 @ W3 ; bc = (b1 @ W2 + b2) @ W3 + b3.  One block, 128 threads.
// ---------------------------------------------------------------------------
__global__ void precompute_kernel(const float* __restrict__ W1, const float* __restrict__ b1,
                                  const float* __restrict__ W2, const float* __restrict__ b2,
                                  const float* __restrict__ W3, const float* __restrict__ b3) {
    __shared__ float sW2[HID * HID];
    __shared__ float sW3[HID * CLS];
    const int t = threadIdx.x;
    for (int i = t; i < HID * HID; i += 128) sW2[i] = W2[i];
    for (int i = t; i < HID * CLS; i += 128) sW3[i] = W3[i];
    __syncthreads();

    // thread k computes row k of Wc
    float v[HID];
#pragma unroll
    for (int j = 0; j < HID; j++) v[j] = 0.f;
#pragma unroll
    for (int p = 0; p < HID; p++) {
        const float w = W1[t * HID + p];
#pragma unroll
        for (int j = 0; j < HID; j++) v[j] = fmaf(w, sW2[p * HID + j], v[j]);
    }
    float w[CLS];
#pragma unroll
    for (int j = 0; j < CLS; j++) w[j] = 0.f;
#pragma unroll
    for (int p = 0; p < HID; p++) {
#pragma unroll
        for (int j = 0; j < CLS; j++) w[j] = fmaf(v[p], sW3[p * CLS + j], w[j]);
    }
#pragma unroll
    for (int j = 0; j < CLS; j++) g_Wc[t * CLS + j] = w[j];

    if (t == 0) {
        float u[HID];
#pragma unroll
        for (int j = 0; j < HID; j++) u[j] = b2[j];
#pragma unroll
        for (int p = 0; p < HID; p++)
#pragma unroll
            for (int j = 0; j < HID; j++) u[j] = fmaf(b1[p], sW2[p * HID + j], u[j]);
        float bb[CLS];
#pragma unroll
        for (int j = 0; j < CLS; j++) bb[j] = b3[j];
#pragma unroll
        for (int p = 0; p < HID; p++)
#pragma unroll
            for (int j = 0; j < CLS; j++) bb[j] = fmaf(u[p], sW3[p * CLS + j], bb[j]);
#pragma unroll
        for (int j = 0; j < CLS; j++) g_bc[j] = bb[j];
    }
}

// ---------------------------------------------------------------------------
// Kernel 1: h = x @ Wc + bc -> g_Hs = fp16(h * sqrt(log2e)).
// One thread per (row, class): 768 CTAs x 256 threads for high occupancy.
// ---------------------------------------------------------------------------
__global__ __launch_bounds__(256)
void mlp_gemm(const float* __restrict__ x) {
    __shared__ float sWc[DIM * CLS];   // 8 KB
    __shared__ float sbc[CLS];

    const int tid = threadIdx.x;
    {
        const float4* src = reinterpret_cast<const float4*>(g_Wc);
        float4* dst = reinterpret_cast<float4*>(sWc);
        dst[tid]       = src[tid];
        dst[tid + 256] = src[tid + 256];
        if (tid < CLS) sbc[tid] = g_bc[tid];
    }
    __syncthreads();

    const int row = blockIdx.x * 16 + (tid >> 4);
    const int j   = tid & 15;

    const float4* xr = reinterpret_cast<const float4*>(x + (size_t)row * DIM);
    float a0 = 0.f, a1 = 0.f, a2 = 0.f, a3 = 0.f;
#pragma unroll
    for (int k4 = 0; k4 < 32; k4++) {
        const float4 xv = __ldg(&xr[k4]);
        a0 = fmaf(xv.x, sWc[(4 * k4 + 0) * CLS + j], a0);
        a1 = fmaf(xv.y, sWc[(4 * k4 + 1) * CLS + j], a1);
        a2 = fmaf(xv.z, sWc[(4 * k4 + 2) * CLS + j], a2);
        a3 = fmaf(xv.w, sWc[(4 * k4 + 3) * CLS + j], a3);
    }
    const float h = (a0 + a1) + (a2 + a3) + sbc[j];

    g_Hs[(size_t)row * HID + j] = __float2half(h * SQRT_LOG2E);
}

// ---------------------------------------------------------------------------
// Kernel 2: fused masked-softmax aggregation on tensor cores (fp16).
// S' = Hs @ Hs^T via f16 HMMA with FP16 accumulators -> packed pairs directly;
// e  = (s'>0) ? 2^s' : 0 via packed f16x2 ex2 + packed mask;
// O' += P @ Hs (f32 accum; scaled by sqrt(log2e), corrected in finalize);
// den via packed HADD2 on the fma pipe.
// 4 CTAs/SM, 576 CTAs = exactly one wave.
// ---------------------------------------------------------------------------
__global__ __launch_bounds__(256, 4)
void agg_kernel() {
    __shared__ __align__(16) __half sHn[CHUNK * S_N];  // Hs[j][hid]
    __shared__ __align__(16) __half sHt[HID * S_T];    // Hs^T[hid][j]

    const int tid  = threadIdx.x;
    const int lane = tid & 31;
    const int wid  = tid >> 5;        // 0..7
    const int g    = lane >> 2;       // 0..7
    const int t4   = lane & 3;        // 0..3

    const int split = blockIdx.y;
    const int rbase = blockIdx.x * ROWS_CTA + wid * 16;
    const int rg  = rbase + g;
    const int rg8 = rg + 8;

    // A-fragment: scaled rows (loop-invariant)
    uint32_t a0 = *reinterpret_cast<const uint32_t*>(g_Hs + (size_t)rg  * HID + 2 * t4);
    uint32_t a1 = *reinterpret_cast<const uint32_t*>(g_Hs + (size_t)rg8 * HID + 2 * t4);
    uint32_t a2 = *reinterpret_cast<const uint32_t*>(g_Hs + (size_t)rg  * HID + 2 * t4 + 8);
    uint32_t a3 = *reinterpret_cast<const uint32_t*>(g_Hs + (size_t)rg8 * HID + 2 * t4 + 8);

    float o00 = 0.f, o01 = 0.f, o02 = 0.f, o03 = 0.f;
    float o10 = 0.f, o11 = 0.f, o12 = 0.f, o13 = 0.f;
    // packed fp16 den accumulators (rows g / g+8 interleaved in pairs)
    __half2 dga = __half2(__ushort_as_half(0), __ushort_as_half(0));
    __half2 dgb = dga;

    const int j0 = split * COLS_PS;

    for (int cc = 0; cc < COLS_PS; cc += CHUNK) {
        __syncthreads();
        // Stage: thread `tid` owns column j = tid of this chunk.
        {
            const int j = tid;
            const size_t gidx = (size_t)(j0 + cc + j) * HID;
            const uint4 vs0 = *reinterpret_cast<const uint4*>(g_Hs + gidx);
            const uint4 vs1 = *reinterpret_cast<const uint4*>(g_Hs + gidx + 8);
            *reinterpret_cast<uint4*>(&sHn[j * S_N])     = vs0;
            *reinterpret_cast<uint4*>(&sHn[j * S_N + 8]) = vs1;

            const uint32_t u[8] = {vs0.x, vs0.y, vs0.z, vs0.w, vs1.x, vs1.y, vs1.z, vs1.w};
#pragma unroll
            for (int w = 0; w < 8; w++) {
                __half2 bp = u2h(u[w]);
                sHt[(2 * w)     * S_T + j] = bp.x;
                sHt[(2 * w + 1) * S_T + j] = bp.y;
            }
        }
        __syncthreads();

#pragma unroll
        for (int kc = 0; kc < CHUNK / 16; kc++) {
            const int ja = 16 * kc + g;
            const int jb = ja + 8;
            uint32_t b0a = *reinterpret_cast<const uint32_t*>(&sHn[ja * S_N + 2 * t4]);
            uint32_t b1a = *reinterpret_cast<const uint32_t*>(&sHn[ja * S_N + 2 * t4 + 8]);
            uint32_t b0b = *reinterpret_cast<const uint32_t*>(&sHn[jb * S_N + 2 * t4]);
            uint32_t b1b = *reinterpret_cast<const uint32_t*>(&sHn[jb * S_N + 2 * t4 + 8]);

            // S-mma with fp16 accumulators: D-fragment IS the packed pair layout
            uint32_t c0a = 0u, c1a = 0u, c0b = 0u, c1b = 0u;
            mma_f16acc(c0a, c1a, a0, a1, a2, a3, b0a, b1a);
            mma_f16acc(c0b, c1b, a0, a1, a2, a3, b0b, b1b);

            // packed masked exp straight off the MMA output
            uint32_t pa0 = masked_exp2h(c0a);   // P[g   ][2t4..]   (n-tile a)
            uint32_t pa1 = masked_exp2h(c1a);   // P[g+8 ][2t4..]
            uint32_t pa2 = masked_exp2h(c0b);   // P[g   ][8+2t4..] (n-tile b)
            uint32_t pa3 = masked_exp2h(c1b);   // P[g+8 ][8+2t4..]

            // den on the fma pipe: 4 HADD2/kc
            dga = __hadd2(dga, __hadd2(u2h(pa0), u2h(pa2)));
            dgb = __hadd2(dgb, __hadd2(u2h(pa1), u2h(pa3)));

            uint32_t q0n0 = *reinterpret_cast<const uint32_t*>(&sHt[g * S_T + 16 * kc + 2 * t4]);
            uint32_t q1n0 = *reinterpret_cast<const uint32_t*>(&sHt[g * S_T + 16 * kc + 2 * t4 + 8]);
            uint32_t q0n1 = *reinterpret_cast<const uint32_t*>(&sHt[(g + 8) * S_T + 16 * kc + 2 * t4]);
            uint32_t q1n1 = *reinterpret_cast<const uint32_t*>(&sHt[(g + 8) * S_T + 16 * kc + 2 * t4 + 8]);

            mma_f16(o00, o01, o02, o03, pa0, pa1, pa2, pa3, q0n0, q1n0);
            mma_f16(o10, o11, o12, o13, pa0, pa1, pa2, pa3, q0n1, q1n1);
        }
    }

    // den epilogue: unpack to f32, reduce across the 4 lanes sharing each row
    float den_g  = __half2float(dga.x) + __half2float(dga.y);
    float den_g8 = __half2float(dgb.x) + __half2float(dgb.y);
    den_g  += __shfl_xor_sync(0xffffffffu, den_g, 1);
    den_g  += __shfl_xor_sync(0xffffffffu, den_g, 2);
    den_g8 += __shfl_xor_sync(0xffffffffu, den_g8, 1);
    den_g8 += __shfl_xor_sync(0xffffffffu, den_g8, 2);

    float* pn  = g_pnum + ((size_t)split * NN + rg) * CLS;
    float* pn8 = g_pnum + ((size_t)split * NN + rg8) * CLS;
    *reinterpret_cast<float2*>(&pn [2 * t4])     = make_float2(o00, o01);
    *reinterpret_cast<float2*>(&pn [2 * t4 + 8]) = make_float2(o10, o11);
    *reinterpret_cast<float2*>(&pn8[2 * t4])     = make_float2(o02, o03);
    *reinterpret_cast<float2*>(&pn8[2 * t4 + 8]) = make_float2(o12, o13);
    if (t4 == 0) {
        g_pden[split * NN + rg]  = den_g;
        g_pden[split * NN + rg8] = den_g8;
    }
}

// ---------------------------------------------------------------------------
// Kernel 3: reduce split partials, out = num/(den*sqrt(log2e)), row log-softmax.
// 8 threads per row; 128-thread blocks (768 CTAs) for latency coverage.
// ---------------------------------------------------------------------------
__global__ __launch_bounds__(128)
void finalize_kernel(float* __restrict__ out) {
    const int idx = blockIdx.x * 128 + threadIdx.x;
    const int row = idx >> 3;
    const int p   = idx & 7;

    float n0 = 0.f, n1 = 0.f, den = 0.f;
#pragma unroll
    for (int s = 0; s < NSPLIT; s++) {
        float2 v = *reinterpret_cast<const float2*>(
            g_pnum + ((size_t)s * NN + row) * CLS + 2 * p);
        n0 += v.x; n1 += v.y;
        den += g_pden[s * NN + row];
    }

    // num is scaled by sqrt(log2e) (O-mma used scaled Hs); correct here.
    const float inv = 1.0f / (den * SQRT_LOG2E);
    float o0 = n0 * inv, o1 = n1 * inv;

    float m = fmaxf(o0, o1);
    m = fmaxf(m, __shfl_xor_sync(0xffffffffu, m, 1));
    m = fmaxf(m, __shfl_xor_sync(0xffffffffu, m, 2));
    m = fmaxf(m, __shfl_xor_sync(0xffffffffu, m, 4));

    float sum = expf(o0 - m) + expf(o1 - m);
    sum += __shfl_xor_sync(0xffffffffu, sum, 1);
    sum += __shfl_xor_sync(0xffffffffu, sum, 2);
    sum += __shfl_xor_sync(0xffffffffu, sum, 4);

    const float lse = logf(sum) + m;
    *reinterpret_cast<float2*>(out + (size_t)row * CLS + 2 * p) =
        make_float2(o0 - lse, o1 - lse);
}

// ---------------------------------------------------------------------------
extern "C" void kernel_launch(void* const* d_in, const int* in_sizes, int n_in,
                              void* d_out, int out_size) {
    const float* x  = (const float*)d_in[0];
    const float* W1 = (const float*)d_in[1];
    const float* b1 = (const float*)d_in[2];
    const float* W2 = (const float*)d_in[3];
    const float* b2 = (const float*)d_in[4];
    const float* W3 = (const float*)d_in[5];
    const float* b3 = (const float*)d_in[6];
    float* out = (float*)d_out;

    precompute_kernel<<<1, 128>>>(W1, b1, W2, b2, W3, b3);
    mlp_gemm<<<NN / 16, 256>>>(x);

    dim3 grid(NN / ROWS_CTA, NSPLIT);
    agg_kernel<<<grid, 256>>>();

    finalize_kernel<<<(NN * 8) / 128, 128>>>(out);
}